// round 9
// baseline (speedup 1.0000x reference)
#include <cuda_runtime.h>
#include <cuda_bf16.h>
#include <math.h>
#include <stdint.h>

// ---------------------------------------------------------------------------
// Problem: x [16,48,207,512], 8 heads, d=64.  M = 158976 rows, K=N=512.
// ---------------------------------------------------------------------------
#define MB   16
#define TT   48
#define NV   207
#define FF   512
#define NHEAD 8
#define HD   64
#define MROWS (MB*TT*NV)          // 158976
#define SZ   ((size_t)MROWS * FF)

__device__ float g_scratch[6 * SZ];

// ---------------------------------------------------------------------------
// helpers
// ---------------------------------------------------------------------------
__device__ __forceinline__ void cp_async16(void* smem, const void* gmem) {
    unsigned s = (unsigned)__cvta_generic_to_shared(smem);
    asm volatile("cp.async.cg.shared.global [%0], [%1], 16;\n" :: "r"(s), "l"(gmem));
}
__device__ __forceinline__ void cp_commit() { asm volatile("cp.async.commit_group;\n" ::: "memory"); }

__device__ __forceinline__ void mma_bf16(float c[4], const uint32_t a[4], const uint32_t* b) {
    asm volatile(
        "mma.sync.aligned.m16n8k16.row.col.f32.bf16.bf16.f32 "
        "{%0,%1,%2,%3}, {%4,%5,%6,%7}, {%8,%9}, {%0,%1,%2,%3};\n"
        : "+f"(c[0]), "+f"(c[1]), "+f"(c[2]), "+f"(c[3])
        : "r"(a[0]), "r"(a[1]), "r"(a[2]), "r"(a[3]), "r"(b[0]), "r"(b[1]));
}
__device__ __forceinline__ void ldsm_x4(uint32_t r[4], uint32_t addr) {
    asm volatile("ldmatrix.sync.aligned.m8n8.x4.shared.b16 {%0,%1,%2,%3}, [%4];"
                 : "=r"(r[0]), "=r"(r[1]), "=r"(r[2]), "=r"(r[3]) : "r"(addr));
}

// ---------------------------------------------------------------------------
// bf16 HMMA GEMM: C = act(A[M,512] @ Bt^T + bias) (+resid)
//   CTA tile 128x256x64, 512 threads (16 warps, 4x4), warp tile 32x64,
//   ldmatrix, 3-stage cp.async pipeline, 1 barrier per k-tile.
//   Halves L2 traffic vs 64x128 tiling (L2-bw was the binding constraint).
//   act: 0 bias->fp32 ; 1 bias+GELU->bf16 ; 2 bias+resid->fp32 ; 3 bias->bf16
// ---------------------------------------------------------------------------
#define BM 128
#define BN 256
#define BK 64
#define LDT 72           // smem row stride in bf16 (BK + 8): 144B
#define KDIM 512
#define KT (KDIM / BK)   // 8
#define NSTAGE 3
#define A_BYTES (BM * LDT * 2)            // 18432
#define B_BYTES (BN * LDT * 2)            // 36864
#define GEMM_SMEM (NSTAGE * (A_BYTES + B_BYTES))   // 165888

__global__ __launch_bounds__(512, 1)
void gemm_bf16(const __nv_bfloat16* __restrict__ A,
               const __nv_bfloat16* __restrict__ Bt,
               const float* __restrict__ bias,
               const float* __restrict__ resid,
               void* __restrict__ C, int ldc, int act)
{
    extern __shared__ __align__(16) uint8_t dsm[];

    const int tid  = threadIdx.x;
    const int m0   = blockIdx.y * BM;
    const int n0   = blockIdx.x * BN;
    const int warp = tid >> 5;
    const int lane = tid & 31;
    const int wm   = (warp >> 2) * 32;   // 4 warps in m, warp tile 32x64
    const int wn   = (warp & 3) * 64;    // 4 warps in n
    const int g    = lane >> 2;
    const int t4   = lane & 3;

    uint8_t* As[NSTAGE];
    uint8_t* Bs[NSTAGE];
    #pragma unroll
    for (int sidx = 0; sidx < NSTAGE; sidx++) {
        As[sidx] = dsm + sidx * A_BYTES;
        Bs[sidx] = dsm + NSTAGE * A_BYTES + sidx * B_BYTES;
    }
    const uint32_t sm_base = (uint32_t)__cvta_generic_to_shared(dsm);

    // ldmatrix lane-address components
    const int lr        = lane & 7;
    const int a_row_off = ((lane >> 3) & 1) * 8;
    const int a_col_off = (lane >> 4) * 8;
    const int b_row_off = (lane >> 4) * 8;
    const int b_col_off = ((lane >> 3) & 1) * 8;

    float c[2][8][4];
    #pragma unroll
    for (int i = 0; i < 2; i++)
        #pragma unroll
        for (int j = 0; j < 8; j++)
            #pragma unroll
            for (int r = 0; r < 4; r++) c[i][j][r] = 0.f;

    // A tile: 128 rows x 8 chunks = 1024 (512 thr -> 2); B: 256 x 8 = 2048 (4)
    auto load_tiles = [&](int kt, int buf) {
        #pragma unroll
        for (int r = 0; r < 2; r++) {
            int ch  = tid + r * 512;
            int row = ch >> 3;
            int col = (ch & 7) * 8;
            cp_async16(As[buf] + row * (LDT * 2) + col * 2,
                       A + (size_t)(m0 + row) * KDIM + kt * BK + col);
        }
        #pragma unroll
        for (int r = 0; r < 4; r++) {
            int ch  = tid + r * 512;
            int row = ch >> 3;
            int col = (ch & 7) * 8;
            cp_async16(Bs[buf] + row * (LDT * 2) + col * 2,
                       Bt + (size_t)(n0 + row) * KDIM + kt * BK + col);
        }
    };

    load_tiles(0, 0); cp_commit();
    load_tiles(1, 1); cp_commit();

    for (int kt = 0; kt < KT; kt++) {
        if (kt < KT - 1) asm volatile("cp.async.wait_group 1;\n" ::: "memory");
        else             asm volatile("cp.async.wait_group 0;\n" ::: "memory");
        __syncthreads();

        if (kt + 2 < KT) {
            load_tiles(kt + 2, (kt + 2) % NSTAGE);
            cp_commit();
        }

        const int buf = kt % NSTAGE;
        const uint32_t a_base = sm_base + buf * A_BYTES;
        const uint32_t b_base = sm_base + NSTAGE * A_BYTES + buf * B_BYTES;

        #pragma unroll
        for (int kk = 0; kk < BK; kk += 16) {
            uint32_t af[2][4];
            #pragma unroll
            for (int i = 0; i < 2; i++)
                ldsm_x4(af[i], a_base +
                        ((wm + i * 16 + lr + a_row_off) * LDT + kk + a_col_off) * 2);
            uint32_t bfr[4][4];
            #pragma unroll
            for (int jp = 0; jp < 4; jp++)
                ldsm_x4(bfr[jp], b_base +
                        ((wn + jp * 16 + lr + b_row_off) * LDT + kk + b_col_off) * 2);
            #pragma unroll
            for (int i = 0; i < 2; i++)
                #pragma unroll
                for (int j = 0; j < 8; j++)
                    mma_bf16(c[i][j], af[i], &bfr[j >> 1][(j & 1) * 2]);
        }
    }

    // ---- epilogue ----
    #pragma unroll
    for (int i = 0; i < 2; i++) {
        int row0 = m0 + wm + i * 16 + g;
        int row1 = row0 + 8;
        #pragma unroll
        for (int j = 0; j < 8; j++) {
            int col = n0 + wn + j * 8 + 2 * t4;
            float b0 = bias[col], b1 = bias[col + 1];
            float v00 = c[i][j][0] + b0;
            float v01 = c[i][j][1] + b1;
            float v10 = c[i][j][2] + b0;
            float v11 = c[i][j][3] + b1;
            if (act == 1 || act == 3) {
                if (act == 1) {
                    v00 = 0.5f * v00 * (1.f + erff(v00 * 0.70710678118654752f));
                    v01 = 0.5f * v01 * (1.f + erff(v01 * 0.70710678118654752f));
                    v10 = 0.5f * v10 * (1.f + erff(v10 * 0.70710678118654752f));
                    v11 = 0.5f * v11 * (1.f + erff(v11 * 0.70710678118654752f));
                }
                __nv_bfloat16* Cb = (__nv_bfloat16*)C;
                *(__nv_bfloat162*)(Cb + (size_t)row0 * ldc + col) = __floats2bfloat162_rn(v00, v01);
                *(__nv_bfloat162*)(Cb + (size_t)row1 * ldc + col) = __floats2bfloat162_rn(v10, v11);
            } else {
                if (act == 2) {
                    const float* r0 = resid + (size_t)row0 * ldc + col;
                    const float* r1 = resid + (size_t)row1 * ldc + col;
                    v00 += r0[0]; v01 += r0[1];
                    v10 += r1[0]; v11 += r1[1];
                }
                float* Cf = (float*)C;
                *(float2*)(Cf + (size_t)row0 * ldc + col) = make_float2(v00, v01);
                *(float2*)(Cf + (size_t)row1 * ldc + col) = make_float2(v10, v11);
            }
        }
    }
}

// ---------------------------------------------------------------------------
// Attention: one block per (head, b, n). Register-blocked 4x4 tiles, float4
// smem loads, warp-parallel softmax.  qkv bf16 [M,1536]; o bf16 [M,512].
// ---------------------------------------------------------------------------
#define LDQ (HD + 4)
#define LDP 52

__global__ __launch_bounds__(256)
void attn_kernel(const __nv_bfloat16* __restrict__ qkv, __nv_bfloat16* __restrict__ o)
{
    __shared__ float qs[TT][LDQ];
    __shared__ float ks[TT][LDQ];
    __shared__ float vs[TT][LDQ];
    __shared__ float ps[TT][LDP];

    const int bid = blockIdx.x;
    const int n   = bid % NV;
    const int b   = (bid / NV) % MB;
    const int h   = bid / (NV * MB);
    const int tid = threadIdx.x;

    const size_t brow  = (size_t)(b * TT) * NV + n;
    const size_t qbase = brow * 1536 + h * HD;
    const size_t tq    = (size_t)NV * 1536;

    for (int idx = tid; idx < TT * (HD / 2); idx += 256) {
        int t = idx >> 5, j2 = idx & 31;
        size_t gofs = qbase + (size_t)t * tq + j2 * 2;
        float2 qv = __bfloat1622float2(*(const __nv_bfloat162*)(qkv + gofs));
        float2 kv = __bfloat1622float2(*(const __nv_bfloat162*)(qkv + gofs + 512));
        float2 vv = __bfloat1622float2(*(const __nv_bfloat162*)(qkv + gofs + 1024));
        qs[t][j2 * 2] = qv.x; qs[t][j2 * 2 + 1] = qv.y;
        ks[t][j2 * 2] = kv.x; ks[t][j2 * 2 + 1] = kv.y;
        vs[t][j2 * 2] = vv.x; vs[t][j2 * 2 + 1] = vv.y;
    }
    __syncthreads();

    // ---- scores: 144 threads, each a 4x4 tile, float4 dot products ----
    if (tid < 144) {
        const int i0 = (tid / 12) * 4;
        const int s0 = (tid % 12) * 4;
        if (s0 <= i0 + 3) {
            float acc[4][4] = {};
            #pragma unroll
            for (int c4 = 0; c4 < HD / 4; c4++) {
                float4 qv[4], kv[4];
                #pragma unroll
                for (int d = 0; d < 4; d++) {
                    qv[d] = *(const float4*)&qs[i0 + d][c4 * 4];
                    kv[d] = *(const float4*)&ks[s0 + d][c4 * 4];
                }
                #pragma unroll
                for (int di = 0; di < 4; di++)
                    #pragma unroll
                    for (int ds = 0; ds < 4; ds++)
                        acc[di][ds] += qv[di].x * kv[ds].x + qv[di].y * kv[ds].y
                                     + qv[di].z * kv[ds].z + qv[di].w * kv[ds].w;
            }
            #pragma unroll
            for (int di = 0; di < 4; di++)
                #pragma unroll
                for (int ds = 0; ds < 4; ds++) {
                    int i = i0 + di, s = s0 + ds;
                    if (s <= i) ps[i][s] = acc[di][ds] * 0.125f;
                }
        }
    }
    __syncthreads();

    // ---- softmax: warp-per-row (8 warps x 6 rows), shfl reductions ----
    {
        const int w = tid >> 5, lane = tid & 31;
        #pragma unroll
        for (int r = 0; r < 6; r++) {
            const int i = w * 6 + r;
            float v0 = (lane <= i) ? ps[i][lane] : -1e30f;
            float v1 = (lane + 32 <= i) ? ps[i][lane + 32] : -1e30f;
            float mx = fmaxf(v0, v1);
            #pragma unroll
            for (int off = 16; off; off >>= 1)
                mx = fmaxf(mx, __shfl_xor_sync(0xFFFFFFFFu, mx, off));
            float e0 = (lane <= i)      ? __expf(v0 - mx) : 0.f;
            float e1 = (lane + 32 <= i) ? __expf(v1 - mx) : 0.f;
            float sum = e0 + e1;
            #pragma unroll
            for (int off = 16; off; off >>= 1)
                sum += __shfl_xor_sync(0xFFFFFFFFu, sum, off);
            float inv = 1.f / sum;
            ps[i][lane] = e0 * inv;                 // masked lanes write exact 0
            if (lane + 32 < TT) ps[i][lane + 32] = e1 * inv;
        }
    }
    __syncthreads();

    // ---- O = P @ V : 192 threads, each a 4x4 tile; causal s-truncation ----
    if (tid < 192) {
        const int i0 = (tid >> 4) * 4;
        const int j0 = (tid & 15) * 4;
        float acc[4][4] = {};
        const int send = i0 + 4;
        for (int s = 0; s < send; s++) {
            float4 vv = *(const float4*)&vs[s][j0];
            #pragma unroll
            for (int di = 0; di < 4; di++) {
                float p = ps[i0 + di][s];
                acc[di][0] += p * vv.x;
                acc[di][1] += p * vv.y;
                acc[di][2] += p * vv.z;
                acc[di][3] += p * vv.w;
            }
        }
        #pragma unroll
        for (int di = 0; di < 4; di++) {
            int i = i0 + di;
            __nv_bfloat16* op = o + (brow + (size_t)i * NV) * FF + h * HD + j0;
            *(__nv_bfloat162*)op       = __floats2bfloat162_rn(acc[di][0], acc[di][1]);
            *(__nv_bfloat162*)(op + 2) = __floats2bfloat162_rn(acc[di][2], acc[di][3]);
        }
    }
}

// ---------------------------------------------------------------------------
// LayerNorm over last dim (512). One block (128 threads) per row.
// ---------------------------------------------------------------------------
__global__ __launch_bounds__(128)
void ln_kernel(const float* __restrict__ h, const float* __restrict__ gamma,
               const float* __restrict__ beta, float* __restrict__ out)
{
    __shared__ float red[8];
    const int row = blockIdx.x;
    const int tid = threadIdx.x;

    float4 val = ((const float4*)(h + (size_t)row * FF))[tid];
    float s  = val.x + val.y + val.z + val.w;
    float ss = val.x * val.x + val.y * val.y + val.z * val.z + val.w * val.w;
    #pragma unroll
    for (int off = 16; off; off >>= 1) {
        s  += __shfl_xor_sync(0xFFFFFFFFu, s,  off);
        ss += __shfl_xor_sync(0xFFFFFFFFu, ss, off);
    }
    if ((tid & 31) == 0) { red[tid >> 5] = s; red[4 + (tid >> 5)] = ss; }
    __syncthreads();
    s  = red[0] + red[1] + red[2] + red[3];
    ss = red[4] + red[5] + red[6] + red[7];

    float mean = s * (1.f / 512.f);
    float var  = ss * (1.f / 512.f) - mean * mean;
    float rstd = rsqrtf(var + 1e-5f);

    float4 gm = ((const float4*)gamma)[tid];
    float4 bt = ((const float4*)beta)[tid];
    float4 r;
    r.x = gm.x * (val.x - mean) * rstd + bt.x;
    r.y = gm.y * (val.y - mean) * rstd + bt.y;
    r.z = gm.z * (val.z - mean) * rstd + bt.z;
    r.w = gm.w * (val.w - mean) * rstd + bt.w;
    ((float4*)(out + (size_t)row * FF))[tid] = r;
}

// ---------------------------------------------------------------------------
// Prep kernels
// ---------------------------------------------------------------------------
__global__ void cvt_x_bf16(const float* __restrict__ x, __nv_bfloat16* __restrict__ xb, int n4)
{
    int i = blockIdx.x * blockDim.x + threadIdx.x;
    if (i < n4) {
        float4 v = ((const float4*)x)[i];
        __nv_bfloat162* o = (__nv_bfloat162*)xb + (size_t)i * 2;
        o[0] = __floats2bfloat162_rn(v.x, v.y);
        o[1] = __floats2bfloat162_rn(v.z, v.w);
    }
}

__global__ void transp_all(const float* __restrict__ Wq, const float* __restrict__ Wk,
                           const float* __restrict__ Wv, const float* __restrict__ W1,
                           const float* __restrict__ W2,
                           __nv_bfloat16* __restrict__ wqkvT,
                           __nv_bfloat16* __restrict__ w1T,
                           __nv_bfloat16* __restrict__ w2T)
{
    __shared__ float t[32][33];
    const float* W;
    __nv_bfloat16* Wt;
    switch (blockIdx.z) {
        case 0: W = Wq; Wt = wqkvT; break;
        case 1: W = Wk; Wt = wqkvT + (size_t)512 * 512; break;
        case 2: W = Wv; Wt = wqkvT + (size_t)1024 * 512; break;
        case 3: W = W1; Wt = w1T; break;
        default: W = W2; Wt = w2T; break;
    }
    int bx = blockIdx.x * 32, by = blockIdx.y * 32;
    int tx = threadIdx.x, ty = threadIdx.y;
    #pragma unroll
    for (int r = 0; r < 32; r += 8)
        t[ty + r][tx] = W[(size_t)(by + ty + r) * 512 + bx + tx];
    __syncthreads();
    #pragma unroll
    for (int r = 0; r < 32; r += 8)
        Wt[(size_t)(bx + ty + r) * 512 + by + tx] = __float2bfloat16(t[tx][ty + r]);
}

__global__ void concat_bias(const float* __restrict__ bq, const float* __restrict__ bk,
                            const float* __restrict__ bv, float* __restrict__ b)
{
    int i = threadIdx.x + blockIdx.x * 256;
    if (i < 512)        b[i] = bq[i];
    else if (i < 1024)  b[i] = bk[i - 512];
    else if (i < 1536)  b[i] = bv[i - 1024];
}

// ---------------------------------------------------------------------------
// Launch
// ---------------------------------------------------------------------------
extern "C" void kernel_launch(void* const* d_in, const int* in_sizes, int n_in,
                              void* d_out, int out_size)
{
    const float* x     = (const float*)d_in[0];
    const float* Wq    = (const float*)d_in[1];
    const float* bq    = (const float*)d_in[2];
    const float* Wk    = (const float*)d_in[3];
    const float* bk    = (const float*)d_in[4];
    const float* Wv    = (const float*)d_in[5];
    const float* bv    = (const float*)d_in[6];
    const float* W1    = (const float*)d_in[7];
    const float* b1    = (const float*)d_in[8];
    const float* W2    = (const float*)d_in[9];
    const float* b2    = (const float*)d_in[10];
    const float* gamma = (const float*)d_in[11];
    const float* beta  = (const float*)d_in[12];
    float* out = (float*)d_out;

    float* s;
    cudaGetSymbolAddress((void**)&s, g_scratch);
    __nv_bfloat16*  qkvb  = (__nv_bfloat16*)s;                     // [M,1536] bf16
    float*          h2    = s + 3 * SZ;                            // [M,512]  fp32
    __nv_bfloat16*  xb    = (__nv_bfloat16*)(s + 4 * SZ);          // [M,512]  bf16
    __nv_bfloat16*  ob    = (__nv_bfloat16*)(s + 4 * SZ + SZ / 2); // [M,512]  bf16
    __nv_bfloat16*  h1b   = (__nv_bfloat16*)(s + 5 * SZ);          // [M,512]  bf16
    __nv_bfloat16*  wqkvT = (__nv_bfloat16*)(s + 5 * SZ + SZ / 2); // [1536,512] bf16
    __nv_bfloat16*  w1T   = wqkvT + (size_t)1536 * 512;
    __nv_bfloat16*  w2T   = w1T   + (size_t)512 * 512;
    float*          bqkv  = (float*)(w2T + (size_t)512 * 512);     // [1536]

    cudaFuncSetAttribute(gemm_bf16, cudaFuncAttributeMaxDynamicSharedMemorySize, GEMM_SMEM);

    // prep
    cvt_x_bf16<<<(int)((SZ / 4 + 255) / 256), 256>>>(x, xb, (int)(SZ / 4));
    transp_all<<<dim3(16, 16, 5), dim3(32, 8)>>>(Wq, Wk, Wv, W1, W2, wqkvT, w1T, w2T);
    concat_bias<<<6, 256>>>(bq, bk, bv, bqkv);

    // fused QKV GEMM -> bf16 qkv
    gemm_bf16<<<dim3(1536 / BN, MROWS / BM), 512, GEMM_SMEM>>>(
        xb, wqkvT, bqkv, nullptr, qkvb, 1536, 3);

    attn_kernel<<<NHEAD * MB * NV, 256>>>(qkvb, ob);

    // FFN1 (+GELU -> bf16)
    gemm_bf16<<<dim3(FF / BN, MROWS / BM), 512, GEMM_SMEM>>>(
        ob, w1T, b1, nullptr, h1b, FF, 1);
    // FFN2 (+bias +residual -> fp32)
    gemm_bf16<<<dim3(FF / BN, MROWS / BM), 512, GEMM_SMEM>>>(
        h1b, w2T, b2, x, h2, FF, 2);

    ln_kernel<<<MROWS, 128>>>(h2, gamma, beta, out);
}

// round 10
// speedup vs baseline: 1.0875x; 1.0875x over previous
#include <cuda_runtime.h>
#include <cuda_bf16.h>
#include <math.h>
#include <stdint.h>

// ---------------------------------------------------------------------------
// Problem: x [16,48,207,512], 8 heads, d=64.  M = 158976 rows, K=N=512.
// ---------------------------------------------------------------------------
#define MB   16
#define TT   48
#define NV   207
#define FF   512
#define NHEAD 8
#define HD   64
#define MROWS (MB*TT*NV)          // 158976
#define SZ   ((size_t)MROWS * FF)

__device__ float g_scratch[6 * SZ];

// ---------------------------------------------------------------------------
// helpers
// ---------------------------------------------------------------------------
__device__ __forceinline__ void cp_async16(void* smem, const void* gmem) {
    unsigned s = (unsigned)__cvta_generic_to_shared(smem);
    asm volatile("cp.async.cg.shared.global [%0], [%1], 16;\n" :: "r"(s), "l"(gmem));
}
__device__ __forceinline__ void cp_commit() { asm volatile("cp.async.commit_group;\n" ::: "memory"); }
__device__ __forceinline__ void cp_wait0()  { asm volatile("cp.async.wait_group 0;\n" ::: "memory"); }

__device__ __forceinline__ void mma_bf16(float c[4], const uint32_t a[4], const uint32_t* b) {
    asm volatile(
        "mma.sync.aligned.m16n8k16.row.col.f32.bf16.bf16.f32 "
        "{%0,%1,%2,%3}, {%4,%5,%6,%7}, {%8,%9}, {%0,%1,%2,%3};\n"
        : "+f"(c[0]), "+f"(c[1]), "+f"(c[2]), "+f"(c[3])
        : "r"(a[0]), "r"(a[1]), "r"(a[2]), "r"(a[3]), "r"(b[0]), "r"(b[1]));
}
__device__ __forceinline__ void ldsm_x4(uint32_t r[4], uint32_t addr) {
    asm volatile("ldmatrix.sync.aligned.m8n8.x4.shared.b16 {%0,%1,%2,%3}, [%4];"
                 : "=r"(r[0]), "=r"(r[1]), "=r"(r[2]), "=r"(r[3]) : "r"(addr));
}

// ---------------------------------------------------------------------------
// bf16 HMMA GEMM: C = act(A[M,512] @ Bt^T + bias) (+resid)
//   CTA tile 64x128x64, 128 threads (4 warps in n), warp tile 64x32, ldmatrix,
//   2-stage cp.async pipeline, 4 CTAs/SM (measured-best config, R8).
//   act: 0 bias->fp32 ; 1 bias+GELU->bf16 ; 2 bias+resid->fp32 ; 3 bias->bf16
// ---------------------------------------------------------------------------
#define BM 64
#define BN 128
#define BK 64
#define LDT 72
#define KDIM 512
#define KT (KDIM / BK)   // 8
#define A_BYTES (BM * LDT * 2)            // 9216
#define B_BYTES (BN * LDT * 2)            // 18432
#define GEMM_SMEM (2 * (A_BYTES + B_BYTES))   // 55296

__global__ __launch_bounds__(128, 4)
void gemm_bf16(const __nv_bfloat16* __restrict__ A,
               const __nv_bfloat16* __restrict__ Bt,
               const float* __restrict__ bias,
               const float* __restrict__ resid,
               void* __restrict__ C, int ldc, int act)
{
    extern __shared__ __align__(16) uint8_t dsm[];

    const int tid  = threadIdx.x;
    const int m0   = blockIdx.y * BM;
    const int n0   = blockIdx.x * BN;
    const int warp = tid >> 5;
    const int lane = tid & 31;
    const int wn   = warp * 32;
    const int g    = lane >> 2;
    const int t4   = lane & 3;

    uint8_t* As[2] = { dsm,                dsm + A_BYTES };
    uint8_t* Bs[2] = { dsm + 2 * A_BYTES,  dsm + 2 * A_BYTES + B_BYTES };
    const uint32_t sm_base = (uint32_t)__cvta_generic_to_shared(dsm);

    const int lr        = lane & 7;
    const int a_row_off = ((lane >> 3) & 1) * 8;
    const int a_col_off = (lane >> 4) * 8;
    const int b_row_off = (lane >> 4) * 8;
    const int b_col_off = ((lane >> 3) & 1) * 8;

    float c[4][4][4];
    #pragma unroll
    for (int i = 0; i < 4; i++)
        #pragma unroll
        for (int j = 0; j < 4; j++)
            #pragma unroll
            for (int r = 0; r < 4; r++) c[i][j][r] = 0.f;

    auto load_tiles = [&](int kt, int buf) {
        #pragma unroll
        for (int r = 0; r < 4; r++) {
            int ch  = tid + r * 128;
            int row = ch >> 3;
            int col = (ch & 7) * 8;
            cp_async16(As[buf] + row * (LDT * 2) + col * 2,
                       A + (size_t)(m0 + row) * KDIM + kt * BK + col);
        }
        #pragma unroll
        for (int r = 0; r < 8; r++) {
            int ch  = tid + r * 128;
            int row = ch >> 3;
            int col = (ch & 7) * 8;
            cp_async16(Bs[buf] + row * (LDT * 2) + col * 2,
                       Bt + (size_t)(n0 + row) * KDIM + kt * BK + col);
        }
    };

    load_tiles(0, 0);
    cp_commit();

    for (int kt = 0; kt < KT; kt++) {
        cp_wait0();
        __syncthreads();
        if (kt + 1 < KT) {
            load_tiles(kt + 1, (kt + 1) & 1);
            cp_commit();
        }
        const int buf = kt & 1;
        const uint32_t a_base = sm_base + buf * A_BYTES;
        const uint32_t b_base = sm_base + 2 * A_BYTES + buf * B_BYTES;

        #pragma unroll
        for (int kk = 0; kk < BK; kk += 16) {
            uint32_t af[4][4];
            #pragma unroll
            for (int i = 0; i < 4; i++)
                ldsm_x4(af[i], a_base +
                        ((i * 16 + lr + a_row_off) * LDT + kk + a_col_off) * 2);
            uint32_t bfr[2][4];
            #pragma unroll
            for (int jp = 0; jp < 2; jp++)
                ldsm_x4(bfr[jp], b_base +
                        ((wn + jp * 16 + lr + b_row_off) * LDT + kk + b_col_off) * 2);
            #pragma unroll
            for (int i = 0; i < 4; i++)
                #pragma unroll
                for (int j = 0; j < 4; j++)
                    mma_bf16(c[i][j], af[i], &bfr[j >> 1][(j & 1) * 2]);
        }
        // NOTE: no trailing __syncthreads — the top-of-iteration wait+barrier
        // already orders buffer reuse in the 2-stage rotation.
    }

    #pragma unroll
    for (int i = 0; i < 4; i++) {
        int row0 = m0 + i * 16 + g;
        int row1 = row0 + 8;
        #pragma unroll
        for (int j = 0; j < 4; j++) {
            int col = n0 + wn + j * 8 + 2 * t4;
            float b0 = bias[col], b1 = bias[col + 1];
            float v00 = c[i][j][0] + b0;
            float v01 = c[i][j][1] + b1;
            float v10 = c[i][j][2] + b0;
            float v11 = c[i][j][3] + b1;
            if (act == 1 || act == 3) {
                if (act == 1) {
                    v00 = 0.5f * v00 * (1.f + erff(v00 * 0.70710678118654752f));
                    v01 = 0.5f * v01 * (1.f + erff(v01 * 0.70710678118654752f));
                    v10 = 0.5f * v10 * (1.f + erff(v10 * 0.70710678118654752f));
                    v11 = 0.5f * v11 * (1.f + erff(v11 * 0.70710678118654752f));
                }
                __nv_bfloat16* Cb = (__nv_bfloat16*)C;
                *(__nv_bfloat162*)(Cb + (size_t)row0 * ldc + col) = __floats2bfloat162_rn(v00, v01);
                *(__nv_bfloat162*)(Cb + (size_t)row1 * ldc + col) = __floats2bfloat162_rn(v10, v11);
            } else {
                if (act == 2) {
                    const float* r0 = resid + (size_t)row0 * ldc + col;
                    const float* r1 = resid + (size_t)row1 * ldc + col;
                    v00 += r0[0]; v01 += r0[1];
                    v10 += r1[0]; v11 += r1[1];
                }
                float* Cf = (float*)C;
                *(float2*)(Cf + (size_t)row0 * ldc + col) = make_float2(v00, v01);
                *(float2*)(Cf + (size_t)row1 * ldc + col) = make_float2(v10, v11);
            }
        }
    }
}

// ---------------------------------------------------------------------------
// Attention: one block per (head, b, n). Register-blocked 4x4 tiles, float4
// smem loads, warp-parallel softmax.  qkv bf16 [M,1536]; o bf16 [M,512].
// ---------------------------------------------------------------------------
#define LDQ (HD + 4)
#define LDP 52

__global__ __launch_bounds__(256)
void attn_kernel(const __nv_bfloat16* __restrict__ qkv, __nv_bfloat16* __restrict__ o)
{
    __shared__ float qs[TT][LDQ];
    __shared__ float ks[TT][LDQ];
    __shared__ float vs[TT][LDQ];
    __shared__ float ps[TT][LDP];

    const int bid = blockIdx.x;
    const int n   = bid % NV;
    const int b   = (bid / NV) % MB;
    const int h   = bid / (NV * MB);
    const int tid = threadIdx.x;

    const size_t brow  = (size_t)(b * TT) * NV + n;
    const size_t qbase = brow * 1536 + h * HD;
    const size_t tq    = (size_t)NV * 1536;

    for (int idx = tid; idx < TT * (HD / 2); idx += 256) {
        int t = idx >> 5, j2 = idx & 31;
        size_t gofs = qbase + (size_t)t * tq + j2 * 2;
        float2 qv = __bfloat1622float2(*(const __nv_bfloat162*)(qkv + gofs));
        float2 kv = __bfloat1622float2(*(const __nv_bfloat162*)(qkv + gofs + 512));
        float2 vv = __bfloat1622float2(*(const __nv_bfloat162*)(qkv + gofs + 1024));
        qs[t][j2 * 2] = qv.x; qs[t][j2 * 2 + 1] = qv.y;
        ks[t][j2 * 2] = kv.x; ks[t][j2 * 2 + 1] = kv.y;
        vs[t][j2 * 2] = vv.x; vs[t][j2 * 2 + 1] = vv.y;
    }
    __syncthreads();

    // ---- scores: 144 threads, each a 4x4 tile, float4 dot products ----
    if (tid < 144) {
        const int i0 = (tid / 12) * 4;
        const int s0 = (tid % 12) * 4;
        if (s0 <= i0 + 3) {
            float acc[4][4] = {};
            #pragma unroll
            for (int c4 = 0; c4 < HD / 4; c4++) {
                float4 qv[4], kv[4];
                #pragma unroll
                for (int d = 0; d < 4; d++) {
                    qv[d] = *(const float4*)&qs[i0 + d][c4 * 4];
                    kv[d] = *(const float4*)&ks[s0 + d][c4 * 4];
                }
                #pragma unroll
                for (int di = 0; di < 4; di++)
                    #pragma unroll
                    for (int ds = 0; ds < 4; ds++)
                        acc[di][ds] += qv[di].x * kv[ds].x + qv[di].y * kv[ds].y
                                     + qv[di].z * kv[ds].z + qv[di].w * kv[ds].w;
            }
            #pragma unroll
            for (int di = 0; di < 4; di++)
                #pragma unroll
                for (int ds = 0; ds < 4; ds++) {
                    int i = i0 + di, s = s0 + ds;
                    if (s <= i) ps[i][s] = acc[di][ds] * 0.125f;
                }
        }
    }
    __syncthreads();

    // ---- softmax: warp-per-row (8 warps x 6 rows), shfl reductions ----
    {
        const int w = tid >> 5, lane = tid & 31;
        #pragma unroll
        for (int r = 0; r < 6; r++) {
            const int i = w * 6 + r;
            float v0 = (lane <= i) ? ps[i][lane] : -1e30f;
            float v1 = (lane + 32 <= i) ? ps[i][lane + 32] : -1e30f;
            float mx = fmaxf(v0, v1);
            #pragma unroll
            for (int off = 16; off; off >>= 1)
                mx = fmaxf(mx, __shfl_xor_sync(0xFFFFFFFFu, mx, off));
            float e0 = (lane <= i)      ? __expf(v0 - mx) : 0.f;
            float e1 = (lane + 32 <= i) ? __expf(v1 - mx) : 0.f;
            float sum = e0 + e1;
            #pragma unroll
            for (int off = 16; off; off >>= 1)
                sum += __shfl_xor_sync(0xFFFFFFFFu, sum, off);
            float inv = 1.f / sum;
            ps[i][lane] = e0 * inv;                 // masked lanes write exact 0
            if (lane + 32 < TT) ps[i][lane + 32] = e1 * inv;
        }
    }
    __syncthreads();

    // ---- O = P @ V : 192 threads, each a 4x4 tile; causal s-truncation ----
    if (tid < 192) {
        const int i0 = (tid >> 4) * 4;
        const int j0 = (tid & 15) * 4;
        float acc[4][4] = {};
        const int send = i0 + 4;
        for (int s = 0; s < send; s++) {
            float4 vv = *(const float4*)&vs[s][j0];
            #pragma unroll
            for (int di = 0; di < 4; di++) {
                float p = ps[i0 + di][s];
                acc[di][0] += p * vv.x;
                acc[di][1] += p * vv.y;
                acc[di][2] += p * vv.z;
                acc[di][3] += p * vv.w;
            }
        }
        #pragma unroll
        for (int di = 0; di < 4; di++) {
            int i = i0 + di;
            __nv_bfloat16* op = o + (brow + (size_t)i * NV) * FF + h * HD + j0;
            *(__nv_bfloat162*)op       = __floats2bfloat162_rn(acc[di][0], acc[di][1]);
            *(__nv_bfloat162*)(op + 2) = __floats2bfloat162_rn(acc[di][2], acc[di][3]);
        }
    }
}

// ---------------------------------------------------------------------------
// LayerNorm over last dim (512). One block (128 threads) per row.
// ---------------------------------------------------------------------------
__global__ __launch_bounds__(128)
void ln_kernel(const float* __restrict__ h, const float* __restrict__ gamma,
               const float* __restrict__ beta, float* __restrict__ out)
{
    __shared__ float red[8];
    const int row = blockIdx.x;
    const int tid = threadIdx.x;

    float4 val = ((const float4*)(h + (size_t)row * FF))[tid];
    float s  = val.x + val.y + val.z + val.w;
    float ss = val.x * val.x + val.y * val.y + val.z * val.z + val.w * val.w;
    #pragma unroll
    for (int off = 16; off; off >>= 1) {
        s  += __shfl_xor_sync(0xFFFFFFFFu, s,  off);
        ss += __shfl_xor_sync(0xFFFFFFFFu, ss, off);
    }
    if ((tid & 31) == 0) { red[tid >> 5] = s; red[4 + (tid >> 5)] = ss; }
    __syncthreads();
    s  = red[0] + red[1] + red[2] + red[3];
    ss = red[4] + red[5] + red[6] + red[7];

    float mean = s * (1.f / 512.f);
    float var  = ss * (1.f / 512.f) - mean * mean;
    float rstd = rsqrtf(var + 1e-5f);

    float4 gm = ((const float4*)gamma)[tid];
    float4 bt = ((const float4*)beta)[tid];
    float4 r;
    r.x = gm.x * (val.x - mean) * rstd + bt.x;
    r.y = gm.y * (val.y - mean) * rstd + bt.y;
    r.z = gm.z * (val.z - mean) * rstd + bt.z;
    r.w = gm.w * (val.w - mean) * rstd + bt.w;
    ((float4*)(out + (size_t)row * FF))[tid] = r;
}

// ---------------------------------------------------------------------------
// Prep kernels
// ---------------------------------------------------------------------------
__global__ void cvt_x_bf16(const float* __restrict__ x, __nv_bfloat16* __restrict__ xb, int n4)
{
    int i = blockIdx.x * blockDim.x + threadIdx.x;
    if (i < n4) {
        float4 v = ((const float4*)x)[i];
        __nv_bfloat162* o = (__nv_bfloat162*)xb + (size_t)i * 2;
        o[0] = __floats2bfloat162_rn(v.x, v.y);
        o[1] = __floats2bfloat162_rn(v.z, v.w);
    }
}

__global__ void transp_all(const float* __restrict__ Wq, const float* __restrict__ Wk,
                           const float* __restrict__ Wv, const float* __restrict__ W1,
                           const float* __restrict__ W2,
                           __nv_bfloat16* __restrict__ wqkvT,
                           __nv_bfloat16* __restrict__ w1T,
                           __nv_bfloat16* __restrict__ w2T)
{
    __shared__ float t[32][33];
    const float* W;
    __nv_bfloat16* Wt;
    switch (blockIdx.z) {
        case 0: W = Wq; Wt = wqkvT; break;
        case 1: W = Wk; Wt = wqkvT + (size_t)512 * 512; break;
        case 2: W = Wv; Wt = wqkvT + (size_t)1024 * 512; break;
        case 3: W = W1; Wt = w1T; break;
        default: W = W2; Wt = w2T; break;
    }
    int bx = blockIdx.x * 32, by = blockIdx.y * 32;
    int tx = threadIdx.x, ty = threadIdx.y;
    #pragma unroll
    for (int r = 0; r < 32; r += 8)
        t[ty + r][tx] = W[(size_t)(by + ty + r) * 512 + bx + tx];
    __syncthreads();
    #pragma unroll
    for (int r = 0; r < 32; r += 8)
        Wt[(size_t)(bx + ty + r) * 512 + by + tx] = __float2bfloat16(t[tx][ty + r]);
}

__global__ void concat_bias(const float* __restrict__ bq, const float* __restrict__ bk,
                            const float* __restrict__ bv, float* __restrict__ b)
{
    int i = threadIdx.x + blockIdx.x * 256;
    if (i < 512)        b[i] = bq[i];
    else if (i < 1024)  b[i] = bk[i - 512];
    else if (i < 1536)  b[i] = bv[i - 1024];
}

// ---------------------------------------------------------------------------
// Launch
// ---------------------------------------------------------------------------
extern "C" void kernel_launch(void* const* d_in, const int* in_sizes, int n_in,
                              void* d_out, int out_size)
{
    const float* x     = (const float*)d_in[0];
    const float* Wq    = (const float*)d_in[1];
    const float* bq    = (const float*)d_in[2];
    const float* Wk    = (const float*)d_in[3];
    const float* bk    = (const float*)d_in[4];
    const float* Wv    = (const float*)d_in[5];
    const float* bv    = (const float*)d_in[6];
    const float* W1    = (const float*)d_in[7];
    const float* b1    = (const float*)d_in[8];
    const float* W2    = (const float*)d_in[9];
    const float* b2    = (const float*)d_in[10];
    const float* gamma = (const float*)d_in[11];
    const float* beta  = (const float*)d_in[12];
    float* out = (float*)d_out;

    float* s;
    cudaGetSymbolAddress((void**)&s, g_scratch);
    __nv_bfloat16*  qkvb  = (__nv_bfloat16*)s;                     // [M,1536] bf16
    float*          h2    = s + 3 * SZ;                            // [M,512]  fp32
    __nv_bfloat16*  xb    = (__nv_bfloat16*)(s + 4 * SZ);          // [M,512]  bf16
    __nv_bfloat16*  ob    = (__nv_bfloat16*)(s + 4 * SZ + SZ / 2); // [M,512]  bf16
    __nv_bfloat16*  h1b   = (__nv_bfloat16*)(s + 5 * SZ);          // [M,512]  bf16
    __nv_bfloat16*  wqkvT = (__nv_bfloat16*)(s + 5 * SZ + SZ / 2); // [1536,512] bf16
    __nv_bfloat16*  w1T   = wqkvT + (size_t)1536 * 512;
    __nv_bfloat16*  w2T   = w1T   + (size_t)512 * 512;
    float*          bqkv  = (float*)(w2T + (size_t)512 * 512);     // [1536]

    cudaFuncSetAttribute(gemm_bf16, cudaFuncAttributeMaxDynamicSharedMemorySize, GEMM_SMEM);

    // prep
    cvt_x_bf16<<<(int)((SZ / 4 + 255) / 256), 256>>>(x, xb, (int)(SZ / 4));
    transp_all<<<dim3(16, 16, 5), dim3(32, 8)>>>(Wq, Wk, Wv, W1, W2, wqkvT, w1T, w2T);
    concat_bias<<<6, 256>>>(bq, bk, bv, bqkv);

    // fused QKV GEMM -> bf16 qkv
    gemm_bf16<<<dim3(1536 / BN, MROWS / BM), 128, GEMM_SMEM>>>(
        xb, wqkvT, bqkv, nullptr, qkvb, 1536, 3);

    attn_kernel<<<NHEAD * MB * NV, 256>>>(qkvb, ob);

    // FFN1 (+GELU -> bf16)
    gemm_bf16<<<dim3(FF / BN, MROWS / BM), 128, GEMM_SMEM>>>(
        ob, w1T, b1, nullptr, h1b, FF, 1);
    // FFN2 (+bias +residual -> fp32)
    gemm_bf16<<<dim3(FF / BN, MROWS / BM), 128, GEMM_SMEM>>>(
        h1b, w2T, b2, x, h2, FF, 2);

    ln_kernel<<<MROWS, 128>>>(h2, gamma, beta, out);
}

// round 11
// speedup vs baseline: 1.0884x; 1.0008x over previous
#include <cuda_runtime.h>
#include <cuda_bf16.h>
#include <math.h>
#include <stdint.h>

// ---------------------------------------------------------------------------
// Problem: x [16,48,207,512], 8 heads, d=64.  M = 158976 rows, K=N=512.
// ---------------------------------------------------------------------------
#define MB   16
#define TT   48
#define NV   207
#define FF   512
#define NHEAD 8
#define HD   64
#define MROWS (MB*TT*NV)          // 158976
#define SZ   ((size_t)MROWS * FF)

__device__ float g_scratch[6 * SZ];

// ---------------------------------------------------------------------------
// helpers
// ---------------------------------------------------------------------------
__device__ __forceinline__ void cp_async16(void* smem, const void* gmem) {
    unsigned s = (unsigned)__cvta_generic_to_shared(smem);
    asm volatile("cp.async.cg.shared.global [%0], [%1], 16;\n" :: "r"(s), "l"(gmem));
}
__device__ __forceinline__ void cp_commit() { asm volatile("cp.async.commit_group;\n" ::: "memory"); }
__device__ __forceinline__ void cp_wait0()  { asm volatile("cp.async.wait_group 0;\n" ::: "memory"); }

__device__ __forceinline__ void mma_bf16(float c[4], const uint32_t a[4], const uint32_t* b) {
    asm volatile(
        "mma.sync.aligned.m16n8k16.row.col.f32.bf16.bf16.f32 "
        "{%0,%1,%2,%3}, {%4,%5,%6,%7}, {%8,%9}, {%0,%1,%2,%3};\n"
        : "+f"(c[0]), "+f"(c[1]), "+f"(c[2]), "+f"(c[3])
        : "r"(a[0]), "r"(a[1]), "r"(a[2]), "r"(a[3]), "r"(b[0]), "r"(b[1]));
}
__device__ __forceinline__ void ldsm_x4(uint32_t r[4], uint32_t addr) {
    asm volatile("ldmatrix.sync.aligned.m8n8.x4.shared.b16 {%0,%1,%2,%3}, [%4];"
                 : "=r"(r[0]), "=r"(r[1]), "=r"(r[2]), "=r"(r[3]) : "r"(addr));
}

// ---------------------------------------------------------------------------
// bf16 HMMA GEMM: C = act(A[M,512] @ Bt^T + bias) (+resid)
//   CTA tile 64x128x64, 128 threads (4 warps in n), warp tile 64x32, ldmatrix,
//   2-stage cp.async pipeline, 4 CTAs/SM (measured-best config).
//   act: 0 bias->fp32 ; 1 bias+GELU->bf16 ; 2 bias+resid->fp32 ; 3 bias->bf16
// ---------------------------------------------------------------------------
#define BM 64
#define BN 128
#define BK 64
#define LDT 72
#define KDIM 512
#define KT (KDIM / BK)   // 8
#define A_BYTES (BM * LDT * 2)            // 9216
#define B_BYTES (BN * LDT * 2)            // 18432
#define GEMM_SMEM (2 * (A_BYTES + B_BYTES))   // 55296

__global__ __launch_bounds__(128, 4)
void gemm_bf16(const __nv_bfloat16* __restrict__ A,
               const __nv_bfloat16* __restrict__ Bt,
               const float* __restrict__ bias,
               const float* __restrict__ resid,
               void* __restrict__ C, int ldc, int act)
{
    extern __shared__ __align__(16) uint8_t dsm[];

    const int tid  = threadIdx.x;
    const int m0   = blockIdx.y * BM;
    const int n0   = blockIdx.x * BN;
    const int warp = tid >> 5;
    const int lane = tid & 31;
    const int wn   = warp * 32;
    const int g    = lane >> 2;
    const int t4   = lane & 3;

    uint8_t* As[2] = { dsm,                dsm + A_BYTES };
    uint8_t* Bs[2] = { dsm + 2 * A_BYTES,  dsm + 2 * A_BYTES + B_BYTES };
    const uint32_t sm_base = (uint32_t)__cvta_generic_to_shared(dsm);

    const int lr        = lane & 7;
    const int a_row_off = ((lane >> 3) & 1) * 8;
    const int a_col_off = (lane >> 4) * 8;
    const int b_row_off = (lane >> 4) * 8;
    const int b_col_off = ((lane >> 3) & 1) * 8;

    float c[4][4][4];
    #pragma unroll
    for (int i = 0; i < 4; i++)
        #pragma unroll
        for (int j = 0; j < 4; j++)
            #pragma unroll
            for (int r = 0; r < 4; r++) c[i][j][r] = 0.f;

    auto load_tiles = [&](int kt, int buf) {
        #pragma unroll
        for (int r = 0; r < 4; r++) {
            int ch  = tid + r * 128;
            int row = ch >> 3;
            int col = (ch & 7) * 8;
            cp_async16(As[buf] + row * (LDT * 2) + col * 2,
                       A + (size_t)(m0 + row) * KDIM + kt * BK + col);
        }
        #pragma unroll
        for (int r = 0; r < 8; r++) {
            int ch  = tid + r * 128;
            int row = ch >> 3;
            int col = (ch & 7) * 8;
            cp_async16(Bs[buf] + row * (LDT * 2) + col * 2,
                       Bt + (size_t)(n0 + row) * KDIM + kt * BK + col);
        }
    };

    load_tiles(0, 0);
    cp_commit();

    for (int kt = 0; kt < KT; kt++) {
        cp_wait0();
        __syncthreads();
        if (kt + 1 < KT) {
            load_tiles(kt + 1, (kt + 1) & 1);
            cp_commit();
        }
        const int buf = kt & 1;
        const uint32_t a_base = sm_base + buf * A_BYTES;
        const uint32_t b_base = sm_base + 2 * A_BYTES + buf * B_BYTES;

        #pragma unroll
        for (int kk = 0; kk < BK; kk += 16) {
            uint32_t af[4][4];
            #pragma unroll
            for (int i = 0; i < 4; i++)
                ldsm_x4(af[i], a_base +
                        ((i * 16 + lr + a_row_off) * LDT + kk + a_col_off) * 2);
            uint32_t bfr[2][4];
            #pragma unroll
            for (int jp = 0; jp < 2; jp++)
                ldsm_x4(bfr[jp], b_base +
                        ((wn + jp * 16 + lr + b_row_off) * LDT + kk + b_col_off) * 2);
            #pragma unroll
            for (int i = 0; i < 4; i++)
                #pragma unroll
                for (int j = 0; j < 4; j++)
                    mma_bf16(c[i][j], af[i], &bfr[j >> 1][(j & 1) * 2]);
        }
        // no trailing __syncthreads (2-stage rotation ordered by top barrier)
    }

    #pragma unroll
    for (int i = 0; i < 4; i++) {
        int row0 = m0 + i * 16 + g;
        int row1 = row0 + 8;
        #pragma unroll
        for (int j = 0; j < 4; j++) {
            int col = n0 + wn + j * 8 + 2 * t4;
            float b0 = bias[col], b1 = bias[col + 1];
            float v00 = c[i][j][0] + b0;
            float v01 = c[i][j][1] + b1;
            float v10 = c[i][j][2] + b0;
            float v11 = c[i][j][3] + b1;
            if (act == 1 || act == 3) {
                if (act == 1) {
                    v00 = 0.5f * v00 * (1.f + erff(v00 * 0.70710678118654752f));
                    v01 = 0.5f * v01 * (1.f + erff(v01 * 0.70710678118654752f));
                    v10 = 0.5f * v10 * (1.f + erff(v10 * 0.70710678118654752f));
                    v11 = 0.5f * v11 * (1.f + erff(v11 * 0.70710678118654752f));
                }
                __nv_bfloat16* Cb = (__nv_bfloat16*)C;
                *(__nv_bfloat162*)(Cb + (size_t)row0 * ldc + col) = __floats2bfloat162_rn(v00, v01);
                *(__nv_bfloat162*)(Cb + (size_t)row1 * ldc + col) = __floats2bfloat162_rn(v10, v11);
            } else {
                if (act == 2) {
                    const float* r0 = resid + (size_t)row0 * ldc + col;
                    const float* r1 = resid + (size_t)row1 * ldc + col;
                    v00 += r0[0]; v01 += r0[1];
                    v10 += r1[0]; v11 += r1[1];
                }
                float* Cf = (float*)C;
                *(float2*)(Cf + (size_t)row0 * ldc + col) = make_float2(v00, v01);
                *(float2*)(Cf + (size_t)row1 * ldc + col) = make_float2(v10, v11);
            }
        }
    }
}

// ---------------------------------------------------------------------------
// Attention: one block per (head, b, n).
//   Score: triangular task list (78 active 4x4 tiles), 2-way k-split within
//          warp (lanes L / L^16), shfl-combined.  ~5 active warps x 8 k-steps.
//   PV:    3x4 tiles -> 256 tasks, exactly full thread utilization.
//   qkv bf16 [M,1536]; o bf16 [M,512].
// ---------------------------------------------------------------------------
#define LDQ (HD + 4)
#define LDP 52

__global__ __launch_bounds__(256)
void attn_kernel(const __nv_bfloat16* __restrict__ qkv, __nv_bfloat16* __restrict__ o)
{
    __shared__ float qs[TT][LDQ];
    __shared__ float ks[TT][LDQ];
    __shared__ float vs[TT][LDQ];
    __shared__ float ps[TT][LDP];

    const int bid = blockIdx.x;
    const int n   = bid % NV;
    const int b   = (bid / NV) % MB;
    const int h   = bid / (NV * MB);
    const int tid = threadIdx.x;

    const size_t brow  = (size_t)(b * TT) * NV + n;
    const size_t qbase = brow * 1536 + h * HD;
    const size_t tq    = (size_t)NV * 1536;

    for (int idx = tid; idx < TT * (HD / 2); idx += 256) {
        int t = idx >> 5, j2 = idx & 31;
        size_t gofs = qbase + (size_t)t * tq + j2 * 2;
        float2 qv = __bfloat1622float2(*(const __nv_bfloat162*)(qkv + gofs));
        float2 kv = __bfloat1622float2(*(const __nv_bfloat162*)(qkv + gofs + 512));
        float2 vv = __bfloat1622float2(*(const __nv_bfloat162*)(qkv + gofs + 1024));
        qs[t][j2 * 2] = qv.x; qs[t][j2 * 2 + 1] = qv.y;
        ks[t][j2 * 2] = kv.x; ks[t][j2 * 2 + 1] = kv.y;
        vs[t][j2 * 2] = vv.x; vs[t][j2 * 2 + 1] = vv.y;
    }
    __syncthreads();

    // ---- scores: 78 tri-indexed 4x4 tiles, 2 lanes/tile (k-halves) ----
    {
        const int w    = tid >> 5;
        const int lane = tid & 31;
        if (w < 5) {                          // tasks 0..79 live in warps 0..4
            const int t  = w * 16 + (lane & 15);
            const int kh = lane >> 4;         // k-half: c4 in [kh*8, kh*8+8)
            float acc[4][4] = {};
            int i0 = 0, s0 = 0;
            const bool active = (t < 78);
            if (active) {
                int a = (int)((sqrtf(8.f * (float)t + 1.f) - 1.f) * 0.5f);
                while ((a + 1) * (a + 2) / 2 <= t) a++;
                while (a * (a + 1) / 2 > t)       a--;
                int c = t - a * (a + 1) / 2;
                i0 = a * 4; s0 = c * 4;
                #pragma unroll
                for (int c4 = 0; c4 < 8; c4++) {
                    const int cb = (kh * 8 + c4) * 4;
                    float4 qv[4], kv[4];
                    #pragma unroll
                    for (int d = 0; d < 4; d++) {
                        qv[d] = *(const float4*)&qs[i0 + d][cb];
                        kv[d] = *(const float4*)&ks[s0 + d][cb];
                    }
                    #pragma unroll
                    for (int di = 0; di < 4; di++)
                        #pragma unroll
                        for (int ds = 0; ds < 4; ds++)
                            acc[di][ds] += qv[di].x * kv[ds].x + qv[di].y * kv[ds].y
                                         + qv[di].z * kv[ds].z + qv[di].w * kv[ds].w;
                }
            }
            // combine k-halves: lane L gets partner L^16's partial
            #pragma unroll
            for (int di = 0; di < 4; di++)
                #pragma unroll
                for (int ds = 0; ds < 4; ds++)
                    acc[di][ds] += __shfl_xor_sync(0xFFFFFFFFu, acc[di][ds], 16);
            if (active && kh == 0) {
                #pragma unroll
                for (int di = 0; di < 4; di++)
                    #pragma unroll
                    for (int ds = 0; ds < 4; ds++) {
                        int i = i0 + di, s = s0 + ds;
                        if (s <= i) ps[i][s] = acc[di][ds] * 0.125f;
                    }
            }
        }
    }
    __syncthreads();

    // ---- softmax: warp-per-row (8 warps x 6 rows), shfl reductions ----
    {
        const int w = tid >> 5, lane = tid & 31;
        #pragma unroll
        for (int r = 0; r < 6; r++) {
            const int i = w * 6 + r;
            float v0 = (lane <= i) ? ps[i][lane] : -1e30f;
            float v1 = (lane + 32 <= i) ? ps[i][lane + 32] : -1e30f;
            float mx = fmaxf(v0, v1);
            #pragma unroll
            for (int off = 16; off; off >>= 1)
                mx = fmaxf(mx, __shfl_xor_sync(0xFFFFFFFFu, mx, off));
            float e0 = (lane <= i)      ? __expf(v0 - mx) : 0.f;
            float e1 = (lane + 32 <= i) ? __expf(v1 - mx) : 0.f;
            float sum = e0 + e1;
            #pragma unroll
            for (int off = 16; off; off >>= 1)
                sum += __shfl_xor_sync(0xFFFFFFFFu, sum, off);
            float inv = 1.f / sum;
            ps[i][lane] = e0 * inv;
            if (lane + 32 < TT) ps[i][lane + 32] = e1 * inv;
        }
    }
    __syncthreads();

    // ---- O = P @ V : 256 threads, 3x4 tiles (16x16 grid), causal trunc ----
    {
        const int i0 = (tid >> 4) * 3;        // 16 i-tiles of 3 rows
        const int j0 = (tid & 15) * 4;        // 16 j-tiles of 4 cols
        float acc[3][4] = {};
        const int send = i0 + 3;              // p[i][s] = 0 for s > i
        for (int s = 0; s < send; s++) {
            float4 vv = *(const float4*)&vs[s][j0];
            #pragma unroll
            for (int di = 0; di < 3; di++) {
                float p = ps[i0 + di][s];
                acc[di][0] += p * vv.x;
                acc[di][1] += p * vv.y;
                acc[di][2] += p * vv.z;
                acc[di][3] += p * vv.w;
            }
        }
        #pragma unroll
        for (int di = 0; di < 3; di++) {
            int i = i0 + di;
            __nv_bfloat16* op = o + (brow + (size_t)i * NV) * FF + h * HD + j0;
            *(__nv_bfloat162*)op       = __floats2bfloat162_rn(acc[di][0], acc[di][1]);
            *(__nv_bfloat162*)(op + 2) = __floats2bfloat162_rn(acc[di][2], acc[di][3]);
        }
    }
}

// ---------------------------------------------------------------------------
// LayerNorm over last dim (512). One block (128 threads) per row.
// ---------------------------------------------------------------------------
__global__ __launch_bounds__(128)
void ln_kernel(const float* __restrict__ h, const float* __restrict__ gamma,
               const float* __restrict__ beta, float* __restrict__ out)
{
    __shared__ float red[8];
    const int row = blockIdx.x;
    const int tid = threadIdx.x;

    float4 val = ((const float4*)(h + (size_t)row * FF))[tid];
    float s  = val.x + val.y + val.z + val.w;
    float ss = val.x * val.x + val.y * val.y + val.z * val.z + val.w * val.w;
    #pragma unroll
    for (int off = 16; off; off >>= 1) {
        s  += __shfl_xor_sync(0xFFFFFFFFu, s,  off);
        ss += __shfl_xor_sync(0xFFFFFFFFu, ss, off);
    }
    if ((tid & 31) == 0) { red[tid >> 5] = s; red[4 + (tid >> 5)] = ss; }
    __syncthreads();
    s  = red[0] + red[1] + red[2] + red[3];
    ss = red[4] + red[5] + red[6] + red[7];

    float mean = s * (1.f / 512.f);
    float var  = ss * (1.f / 512.f) - mean * mean;
    float rstd = rsqrtf(var + 1e-5f);

    float4 gm = ((const float4*)gamma)[tid];
    float4 bt = ((const float4*)beta)[tid];
    float4 r;
    r.x = gm.x * (val.x - mean) * rstd + bt.x;
    r.y = gm.y * (val.y - mean) * rstd + bt.y;
    r.z = gm.z * (val.z - mean) * rstd + bt.z;
    r.w = gm.w * (val.w - mean) * rstd + bt.w;
    ((float4*)(out + (size_t)row * FF))[tid] = r;
}

// ---------------------------------------------------------------------------
// Prep kernels
// ---------------------------------------------------------------------------
__global__ void cvt_x_bf16(const float* __restrict__ x, __nv_bfloat16* __restrict__ xb, int n4)
{
    int i = blockIdx.x * blockDim.x + threadIdx.x;
    if (i < n4) {
        float4 v = ((const float4*)x)[i];
        __nv_bfloat162* o = (__nv_bfloat162*)xb + (size_t)i * 2;
        o[0] = __floats2bfloat162_rn(v.x, v.y);
        o[1] = __floats2bfloat162_rn(v.z, v.w);
    }
}

__global__ void transp_all(const float* __restrict__ Wq, const float* __restrict__ Wk,
                           const float* __restrict__ Wv, const float* __restrict__ W1,
                           const float* __restrict__ W2,
                           __nv_bfloat16* __restrict__ wqkvT,
                           __nv_bfloat16* __restrict__ w1T,
                           __nv_bfloat16* __restrict__ w2T)
{
    __shared__ float t[32][33];
    const float* W;
    __nv_bfloat16* Wt;
    switch (blockIdx.z) {
        case 0: W = Wq; Wt = wqkvT; break;
        case 1: W = Wk; Wt = wqkvT + (size_t)512 * 512; break;
        case 2: W = Wv; Wt = wqkvT + (size_t)1024 * 512; break;
        case 3: W = W1; Wt = w1T; break;
        default: W = W2; Wt = w2T; break;
    }
    int bx = blockIdx.x * 32, by = blockIdx.y * 32;
    int tx = threadIdx.x, ty = threadIdx.y;
    #pragma unroll
    for (int r = 0; r < 32; r += 8)
        t[ty + r][tx] = W[(size_t)(by + ty + r) * 512 + bx + tx];
    __syncthreads();
    #pragma unroll
    for (int r = 0; r < 32; r += 8)
        Wt[(size_t)(bx + ty + r) * 512 + by + tx] = __float2bfloat16(t[tx][ty + r]);
}

__global__ void concat_bias(const float* __restrict__ bq, const float* __restrict__ bk,
                            const float* __restrict__ bv, float* __restrict__ b)
{
    int i = threadIdx.x + blockIdx.x * 256;
    if (i < 512)        b[i] = bq[i];
    else if (i < 1024)  b[i] = bk[i - 512];
    else if (i < 1536)  b[i] = bv[i - 1024];
}

// ---------------------------------------------------------------------------
// Launch
// ---------------------------------------------------------------------------
extern "C" void kernel_launch(void* const* d_in, const int* in_sizes, int n_in,
                              void* d_out, int out_size)
{
    const float* x     = (const float*)d_in[0];
    const float* Wq    = (const float*)d_in[1];
    const float* bq    = (const float*)d_in[2];
    const float* Wk    = (const float*)d_in[3];
    const float* bk    = (const float*)d_in[4];
    const float* Wv    = (const float*)d_in[5];
    const float* bv    = (const float*)d_in[6];
    const float* W1    = (const float*)d_in[7];
    const float* b1    = (const float*)d_in[8];
    const float* W2    = (const float*)d_in[9];
    const float* b2    = (const float*)d_in[10];
    const float* gamma = (const float*)d_in[11];
    const float* beta  = (const float*)d_in[12];
    float* out = (float*)d_out;

    float* s;
    cudaGetSymbolAddress((void**)&s, g_scratch);
    __nv_bfloat16*  qkvb  = (__nv_bfloat16*)s;                     // [M,1536] bf16
    float*          h2    = s + 3 * SZ;                            // [M,512]  fp32
    __nv_bfloat16*  xb    = (__nv_bfloat16*)(s + 4 * SZ);          // [M,512]  bf16
    __nv_bfloat16*  ob    = (__nv_bfloat16*)(s + 4 * SZ + SZ / 2); // [M,512]  bf16
    __nv_bfloat16*  h1b   = (__nv_bfloat16*)(s + 5 * SZ);          // [M,512]  bf16
    __nv_bfloat16*  wqkvT = (__nv_bfloat16*)(s + 5 * SZ + SZ / 2); // [1536,512] bf16
    __nv_bfloat16*  w1T   = wqkvT + (size_t)1536 * 512;
    __nv_bfloat16*  w2T   = w1T   + (size_t)512 * 512;
    float*          bqkv  = (float*)(w2T + (size_t)512 * 512);     // [1536]

    cudaFuncSetAttribute(gemm_bf16, cudaFuncAttributeMaxDynamicSharedMemorySize, GEMM_SMEM);

    // prep
    cvt_x_bf16<<<(int)((SZ / 4 + 255) / 256), 256>>>(x, xb, (int)(SZ / 4));
    transp_all<<<dim3(16, 16, 5), dim3(32, 8)>>>(Wq, Wk, Wv, W1, W2, wqkvT, w1T, w2T);
    concat_bias<<<6, 256>>>(bq, bk, bv, bqkv);

    // fused QKV GEMM -> bf16 qkv
    gemm_bf16<<<dim3(1536 / BN, MROWS / BM), 128, GEMM_SMEM>>>(
        xb, wqkvT, bqkv, nullptr, qkvb, 1536, 3);

    attn_kernel<<<NHEAD * MB * NV, 256>>>(qkvb, ob);

    // FFN1 (+GELU -> bf16)
    gemm_bf16<<<dim3(FF / BN, MROWS / BM), 128, GEMM_SMEM>>>(
        ob, w1T, b1, nullptr, h1b, FF, 1);
    // FFN2 (+bias +residual -> fp32)
    gemm_bf16<<<dim3(FF / BN, MROWS / BM), 128, GEMM_SMEM>>>(
        h1b, w2T, b2, x, h2, FF, 2);

    ln_kernel<<<MROWS, 128>>>(h2, gamma, beta, out);
}